// round 2
// baseline (speedup 1.0000x reference)
#include <cuda_runtime.h>
#include <math.h>

#define BB 8
#define SS 1024
#define DD 512
#define HH 8
#define DKK 64
#define DFFN 2048
#define MROWS (BB*SS)          /* 8192 */
#define SD (SS*DD)             /* 524288 */

// ---------------- scratch (static device globals; no runtime alloc) --------
__device__ float g_q  [MROWS*DD];
__device__ float g_k  [MROWS*DD];
__device__ float g_v  [MROWS*DD];
__device__ float g_att[MROWS*DD];
__device__ float g_res[MROWS*DD];
__device__ float g_x1 [MROWS*DD];
__device__ float g_x2 [MROWS*DD];
__device__ float g_ff [MROWS*DFFN];
__device__ float g_psum  [BB*256];
__device__ float g_psumsq[BB*256];
__device__ float g_mr[2*BB];

// ---------------- GEMM: C[M,N] = A[M,K] @ W' + epilogue --------------------
// BMODE 0: "HEADS"  W is [H, K, 64]; logical B[kk][n] = W[(n>>6)*K*64 + kk*64 + (n&63)]
// BMODE 1: "TRANS"  W is [N, K];     logical B[kk][n] = W[n*K + kk]
// EPI 0: +bias[n] ; EPI 1: +bias[n]+resid[m,n] ; EPI 2: relu(+bias[n])
template<int BMODE, int EPI>
__global__ void __launch_bounds__(256) gemm_kernel(
    const float* __restrict__ A, const float* __restrict__ W,
    const float* __restrict__ bias, const float* __restrict__ resid,
    float* __restrict__ C, int M, int N, int K)
{
    __shared__ float As[16][128];
    __shared__ float Bs[16][128];
    const int bm = blockIdx.y * 128;
    const int bn = blockIdx.x * 128;
    const int tid = threadIdx.x;
    const int tr = (tid >> 4) << 3;   // 0..120
    const int tc = (tid & 15) << 3;   // 0..120

    float acc[8][8];
#pragma unroll
    for (int i = 0; i < 8; i++)
#pragma unroll
        for (int j = 0; j < 8; j++) acc[i][j] = 0.f;

    const int ar = tid >> 2;          // 0..63
    const int ak = (tid & 3) << 2;    // 0,4,8,12

    for (int k0 = 0; k0 < K; k0 += 16) {
        // ---- load A tile (128x16) ----
#pragma unroll
        for (int i = 0; i < 2; i++) {
            int r = ar + i * 64;
            float4 a = *reinterpret_cast<const float4*>(
                &A[(size_t)(bm + r) * K + k0 + ak]);
            As[ak + 0][r] = a.x; As[ak + 1][r] = a.y;
            As[ak + 2][r] = a.z; As[ak + 3][r] = a.w;
        }
        // ---- load B tile (16x128) ----
        if (BMODE == 0) {
            int kk = tid >> 4;            // 0..15
            int n  = (tid & 15) << 3;     // 0..120
            int gn = bn + n;
            const float* wp = &W[(size_t)(gn >> 6) * (size_t)K * 64
                                 + (size_t)(k0 + kk) * 64 + (gn & 63)];
            float4 b0 = *reinterpret_cast<const float4*>(wp);
            float4 b1 = *reinterpret_cast<const float4*>(wp + 4);
            Bs[kk][n + 0] = b0.x; Bs[kk][n + 1] = b0.y;
            Bs[kk][n + 2] = b0.z; Bs[kk][n + 3] = b0.w;
            Bs[kk][n + 4] = b1.x; Bs[kk][n + 5] = b1.y;
            Bs[kk][n + 6] = b1.z; Bs[kk][n + 7] = b1.w;
        } else {
#pragma unroll
            for (int i = 0; i < 2; i++) {
                int n = (tid >> 2) + i * 64;
                float4 b = *reinterpret_cast<const float4*>(
                    &W[(size_t)(bn + n) * K + k0 + ak]);
                Bs[ak + 0][n] = b.x; Bs[ak + 1][n] = b.y;
                Bs[ak + 2][n] = b.z; Bs[ak + 3][n] = b.w;
            }
        }
        __syncthreads();
        // ---- compute ----
#pragma unroll
        for (int kk = 0; kk < 16; kk++) {
            float4 a0 = *reinterpret_cast<const float4*>(&As[kk][tr]);
            float4 a1 = *reinterpret_cast<const float4*>(&As[kk][tr + 4]);
            float4 b0 = *reinterpret_cast<const float4*>(&Bs[kk][tc]);
            float4 b1 = *reinterpret_cast<const float4*>(&Bs[kk][tc + 4]);
            float ra[8] = {a0.x, a0.y, a0.z, a0.w, a1.x, a1.y, a1.z, a1.w};
            float rb[8] = {b0.x, b0.y, b0.z, b0.w, b1.x, b1.y, b1.z, b1.w};
#pragma unroll
            for (int i = 0; i < 8; i++)
#pragma unroll
                for (int j = 0; j < 8; j++)
                    acc[i][j] += ra[i] * rb[j];
        }
        __syncthreads();
    }
    // ---- epilogue ----
#pragma unroll
    for (int i = 0; i < 8; i++) {
        int row = bm + tr + i;
#pragma unroll
        for (int j = 0; j < 8; j++) {
            int col = bn + tc + j;
            float v = acc[i][j] + bias[col];
            if (EPI == 2) v = fmaxf(v, 0.f);
            if (EPI == 1) v += resid[(size_t)row * N + col];
            C[(size_t)row * N + col] = v;
        }
    }
}

// ---------------- attention: flash-style, 1 warp = 1 query ------------------
// Q,K,V layout: [B,S, H*64]; O same. mask: [B,S] over keys.
__global__ void __launch_bounds__(256) attn_kernel(
    const float* __restrict__ Q, const float* __restrict__ K,
    const float* __restrict__ V, const int* __restrict__ mask,
    float* __restrict__ O)
{
    __shared__ float q_s[8][64];
    __shared__ float k_s[32][65];
    __shared__ float v_s[32][65];
    __shared__ float p_s[8][32];
    __shared__ int   m_s[32];

    const int bh = blockIdx.x;
    const int b = bh >> 3, h = bh & 7;
    const int q0 = blockIdx.y * 8;
    const int tid = threadIdx.x;
    const int w = tid >> 5, lane = tid & 31;

#pragma unroll
    for (int i = 0; i < 2; i++) {
        int idx = tid + i * 256;
        int r = idx >> 6, d = idx & 63;
        q_s[r][d] = Q[(size_t)(b * SS + q0 + r) * 512 + h * 64 + d];
    }

    float m = -INFINITY, l = 0.f, o0 = 0.f, o1 = 0.f;

    for (int kc = 0; kc < SS; kc += 32) {
        __syncthreads();
#pragma unroll
        for (int i = 0; i < 8; i++) {
            int idx = tid + i * 256;
            int r = idx >> 6, d = idx & 63;
            size_t g = (size_t)(b * SS + kc + r) * 512 + h * 64 + d;
            k_s[r][d] = K[g];
            v_s[r][d] = V[g];
        }
        if (tid < 32) m_s[tid] = mask[b * SS + kc + tid];
        __syncthreads();

        float s = 0.f;
#pragma unroll
        for (int d = 0; d < 64; d++) s += q_s[w][d] * k_s[lane][d];
        s *= 0.125f;
        if (m_s[lane] == 0) s = -1e10f;

        float mx = s;
#pragma unroll
        for (int o = 16; o; o >>= 1)
            mx = fmaxf(mx, __shfl_xor_sync(0xffffffffu, mx, o));
        float m_new = fmaxf(m, mx);
        float scale = __expf(m - m_new);        // m=-inf first iter -> 0
        float p = __expf(s - m_new);
        float ps = p;
#pragma unroll
        for (int o = 16; o; o >>= 1)
            ps += __shfl_xor_sync(0xffffffffu, ps, o);
        l = l * scale + ps;
        o0 *= scale; o1 *= scale;
        p_s[w][lane] = p;
        __syncwarp();
#pragma unroll
        for (int j = 0; j < 32; j++) {
            float pj = p_s[w][j];
            o0 += pj * v_s[j][lane];
            o1 += pj * v_s[j][lane + 32];
        }
        m = m_new;
    }
    float inv = 1.f / l;
    size_t ob = (size_t)(b * SS + q0 + w) * 512 + h * 64;
    O[ob + lane]      = o0 * inv;
    O[ob + lane + 32] = o1 * inv;
}

// ---------------- LayerNorm over [S,D] per batch ---------------------------
__global__ void __launch_bounds__(256) ln_partial_kernel(const float* __restrict__ X)
{
    int b = blockIdx.x >> 8;
    int c = blockIdx.x & 255;
    int tid = threadIdx.x;
    const float* p = X + (size_t)b * SD + (size_t)c * 2048;
    float s = 0.f, s2 = 0.f;
#pragma unroll
    for (int i = 0; i < 8; i++) {
        float v = p[tid + i * 256];
        s += v; s2 += v * v;
    }
    __shared__ float sh[256], sh2[256];
    sh[tid] = s; sh2[tid] = s2;
    __syncthreads();
    for (int o = 128; o; o >>= 1) {
        if (tid < o) { sh[tid] += sh[tid + o]; sh2[tid] += sh2[tid + o]; }
        __syncthreads();
    }
    if (tid == 0) { g_psum[blockIdx.x] = sh[0]; g_psumsq[blockIdx.x] = sh2[0]; }
}

__global__ void __launch_bounds__(256) ln_final_kernel()
{
    int b = blockIdx.x;
    int tid = threadIdx.x;
    __shared__ float sh[256], sh2[256];
    sh[tid] = g_psum[b * 256 + tid];
    sh2[tid] = g_psumsq[b * 256 + tid];
    __syncthreads();
    for (int o = 128; o; o >>= 1) {
        if (tid < o) { sh[tid] += sh[tid + o]; sh2[tid] += sh2[tid + o]; }
        __syncthreads();
    }
    if (tid == 0) {
        float inv_n = 1.f / (float)SD;
        float mean = sh[0] * inv_n;
        float var = sh2[0] * inv_n - mean * mean;
        g_mr[2 * b] = mean;
        g_mr[2 * b + 1] = rsqrtf(var + 1e-6f);
    }
}

__global__ void __launch_bounds__(256) ln_apply_kernel(
    const float* __restrict__ X, const float* __restrict__ w,
    const float* __restrict__ bb, float* __restrict__ Y)
{
    int i4 = blockIdx.x * 256 + threadIdx.x;     // 4 floats per thread
    size_t base = (size_t)i4 * 4;
    int b = (int)(base / SD);
    size_t sd = base % SD;
    float mean = g_mr[2 * b], rstd = g_mr[2 * b + 1];
    float4 xv = *reinterpret_cast<const float4*>(X + base);
    float4 wv = *reinterpret_cast<const float4*>(w + sd);
    float4 bv = *reinterpret_cast<const float4*>(bb + sd);
    float4 yv;
    yv.x = (xv.x - mean) * rstd * wv.x + bv.x;
    yv.y = (xv.y - mean) * rstd * wv.y + bv.y;
    yv.z = (xv.z - mean) * rstd * wv.z + bv.z;
    yv.w = (xv.w - mean) * rstd * wv.w + bv.w;
    *reinterpret_cast<float4*>(Y + base) = yv;
}

// ---------------- driver ---------------------------------------------------
static void run_ln(const float* X, const float* w, const float* b, float* Y)
{
    ln_partial_kernel<<<BB * 256, 256>>>(X);
    ln_final_kernel<<<BB, 256>>>();
    ln_apply_kernel<<<SD * BB / 1024, 256>>>(X, w, b, Y);
}

extern "C" void kernel_launch(void* const* d_in, const int* in_sizes, int n_in,
                              void* d_out, int out_size)
{
    const float* x        = (const float*)d_in[0];
    const float* y        = (const float*)d_in[1];
    const int*   src_mask = (const int*)  d_in[2];
    const int*   trg_mask = (const int*)  d_in[3];
    const float* m1_wq = (const float*)d_in[4];
    const float* m1_bq = (const float*)d_in[5];
    const float* m1_wk = (const float*)d_in[6];
    const float* m1_bk = (const float*)d_in[7];
    const float* m1_wv = (const float*)d_in[8];
    const float* m1_bv = (const float*)d_in[9];
    const float* m1_wo = (const float*)d_in[10];
    const float* m1_bo = (const float*)d_in[11];
    const float* m2_wq = (const float*)d_in[12];
    const float* m2_bq = (const float*)d_in[13];
    const float* m2_wk = (const float*)d_in[14];
    const float* m2_bk = (const float*)d_in[15];
    const float* m2_wv = (const float*)d_in[16];
    const float* m2_bv = (const float*)d_in[17];
    const float* m2_wo = (const float*)d_in[18];
    const float* m2_bo = (const float*)d_in[19];
    const float* pw1   = (const float*)d_in[20];
    const float* pb1   = (const float*)d_in[21];
    const float* pw2   = (const float*)d_in[22];
    const float* pb2   = (const float*)d_in[23];
    const float* ln1_w = (const float*)d_in[24];
    const float* ln1_b = (const float*)d_in[25];
    const float* ln2_w = (const float*)d_in[26];
    const float* ln2_b = (const float*)d_in[27];
    const float* ln3_w = (const float*)d_in[28];
    const float* ln3_b = (const float*)d_in[29];
    float* out = (float*)d_out;

    float *q, *k, *v, *att, *res, *x1, *x2, *ff;
    cudaGetSymbolAddress((void**)&q,   g_q);
    cudaGetSymbolAddress((void**)&k,   g_k);
    cudaGetSymbolAddress((void**)&v,   g_v);
    cudaGetSymbolAddress((void**)&att, g_att);
    cudaGetSymbolAddress((void**)&res, g_res);
    cudaGetSymbolAddress((void**)&x1,  g_x1);
    cudaGetSymbolAddress((void**)&x2,  g_x2);
    cudaGetSymbolAddress((void**)&ff,  g_ff);

    dim3 gProj(4, 64);       // N=512
    dim3 gFf1(16, 64);       // N=2048
    dim3 gAttn(BB * HH, SS / 8);

    // ---- stage 1: self-attention ----
    gemm_kernel<0, 0><<<gProj, 256>>>(x, m1_wq, m1_bq, nullptr, q, MROWS, 512, 512);
    gemm_kernel<0, 0><<<gProj, 256>>>(x, m1_wk, m1_bk, nullptr, k, MROWS, 512, 512);
    gemm_kernel<0, 0><<<gProj, 256>>>(x, m1_wv, m1_bv, nullptr, v, MROWS, 512, 512);
    attn_kernel<<<gAttn, 256>>>(q, k, v, trg_mask, att);
    gemm_kernel<1, 1><<<gProj, 256>>>(att, m1_wo, m1_bo, x, res, MROWS, 512, 512);
    run_ln(res, ln1_w, ln1_b, x1);

    // ---- stage 2: cross-attention ----
    gemm_kernel<0, 0><<<gProj, 256>>>(x1, m2_wq, m2_bq, nullptr, q, MROWS, 512, 512);
    gemm_kernel<0, 0><<<gProj, 256>>>(y,  m2_wk, m2_bk, nullptr, k, MROWS, 512, 512);
    gemm_kernel<0, 0><<<gProj, 256>>>(y,  m2_wv, m2_bv, nullptr, v, MROWS, 512, 512);
    attn_kernel<<<gAttn, 256>>>(q, k, v, src_mask, att);
    gemm_kernel<1, 1><<<gProj, 256>>>(att, m2_wo, m2_bo, x1, res, MROWS, 512, 512);
    run_ln(res, ln2_w, ln2_b, x2);

    // ---- stage 3: FFN ----
    gemm_kernel<1, 2><<<gFf1, 256>>>(x2, pw1, pb1, nullptr, ff, MROWS, DFFN, 512);
    gemm_kernel<1, 1><<<gProj, 256>>>(ff, pw2, pb2, x2, res, MROWS, 512, DFFN);
    run_ln(res, ln3_w, ln3_b, out);
}

// round 4
// speedup vs baseline: 4.0492x; 4.0492x over previous
#include <cuda_runtime.h>
#include <cuda_bf16.h>
#include <math.h>
#include <stdint.h>

#define BB 8
#define SS 1024
#define DD 512
#define HH 8
#define DFFN 2048
#define MROWS (BB*SS)
#define SD (SS*DD)
#define NBH (BB*HH)
typedef __nv_bfloat16 bf;

// ---------------- scratch ---------------------------------------------------
__device__ __align__(128) float g_q  [MROWS*DD];
__device__ __align__(128) float g_k  [MROWS*DD];
__device__ __align__(128) float g_v  [MROWS*DD];
__device__ __align__(128) float g_att[MROWS*DD];
__device__ __align__(128) float g_res[MROWS*DD];
__device__ __align__(128) float g_x1 [MROWS*DD];
__device__ __align__(128) float g_x2 [MROWS*DD];
__device__ __align__(128) float g_ff [MROWS*DFFN];
__device__ __align__(128) float g_S  [(size_t)NBH*SS*SS];
__device__ __align__(128) bf g_ahh[MROWS*DFFN];
__device__ __align__(128) bf g_all[MROWS*DFFN];
__device__ __align__(128) bf g_bhh[DFFN*DD];
__device__ __align__(128) bf g_bll[DFFN*DD];
__device__ __align__(128) bf g_qh [NBH*SS*64];
__device__ __align__(128) bf g_ql [NBH*SS*64];
__device__ __align__(128) bf g_kh [NBH*SS*64];
__device__ __align__(128) bf g_kl [NBH*SS*64];
__device__ __align__(128) bf g_vth[NBH*64*SS];
__device__ __align__(128) bf g_vtl[NBH*64*SS];
__device__ __align__(128) bf g_ph [(size_t)NBH*SS*SS];
__device__ __align__(128) bf g_pl [(size_t)NBH*SS*SS];
__device__ float g_psum[BB*256], g_psumsq[BB*256], g_mr[2*BB];

// ---------------- helpers ---------------------------------------------------
__device__ __forceinline__ uint32_t smem_u32(const void* p) {
    uint32_t a;
    asm("{ .reg .u64 t; cvta.to.shared.u64 t, %1; cvt.u32.u64 %0, t; }" : "=r"(a) : "l"(p));
    return a;
}
// swizzled element offset inside a [rows][32]-bf16 tile (16B chunk rotation,
// Gray-code over rows so 8 consecutive 64B rows hit 8 distinct 16B slots)
__device__ __forceinline__ int swz(int r, int c) {
    return r * 32 + ((((c >> 3) ^ ((r ^ (r >> 1)) & 3)) << 3) | (c & 7));
}
__device__ __forceinline__ void cpa16(uint32_t d, const void* s) {
    asm volatile("cp.async.cg.shared.global [%0], [%1], 16;" :: "r"(d), "l"(s));
}
__device__ __forceinline__ void ldsm4(uint32_t* r, uint32_t a) {
    asm volatile("ldmatrix.sync.aligned.m8n8.x4.shared.b16 {%0,%1,%2,%3}, [%4];"
        : "=r"(r[0]), "=r"(r[1]), "=r"(r[2]), "=r"(r[3]) : "r"(a));
}
__device__ __forceinline__ void hmma(float* d, const uint32_t* a, const uint32_t* b) {
    asm volatile("mma.sync.aligned.m16n8k16.row.col.f32.bf16.bf16.f32 "
        "{%0,%1,%2,%3}, {%4,%5,%6,%7}, {%8,%9}, {%0,%1,%2,%3};"
        : "+f"(d[0]), "+f"(d[1]), "+f"(d[2]), "+f"(d[3])
        : "r"(a[0]), "r"(a[1]), "r"(a[2]), "r"(a[3]), "r"(b[0]), "r"(b[1]));
}

// ---------------- HMMA split-bf16 GEMM --------------------------------------
// C[.,N] = (Ah+Al)[.,K] @ (Bh+Bl)[N,K]^T ; batched over blockIdx.z
// EPI: 0 +bias, 1 +bias+resid, 2 relu(+bias), 3 raw
template<int BN, int EPI>
__global__ void __launch_bounds__(256) mma_gemm(
    const bf* __restrict__ Ahp, const bf* __restrict__ Alp,
    const bf* __restrict__ Bhp, const bf* __restrict__ Blp,
    const float* __restrict__ bias, const float* __restrict__ resid,
    float* __restrict__ C, int K, int ldc,
    long long sAz, long long sBz, long long sCzh, long long sCzl, int zshift)
{
    constexpr int BM = 128;
    constexpr int TN = BN / 16;            // n8-tiles per warp
    constexpr int AE = BM * 32, BE = BN * 32, OFF_B = 4 * AE;
    extern __shared__ __align__(16) bf sm[];
    const int tid = threadIdx.x, lane = tid & 31, wid = tid >> 5;
    const int wm = wid & 3, wn = wid >> 2;
    const int z = blockIdx.z, bm = blockIdx.y * BM, bn = blockIdx.x * BN;
    const bf* gA[2] = { Ahp + (long long)z * sAz + (long long)bm * K,
                        Alp + (long long)z * sAz + (long long)bm * K };
    const bf* gB[2] = { Bhp + (long long)z * sBz + (long long)bn * K,
                        Blp + (long long)z * sBz + (long long)bn * K };
    const uint32_t smb = smem_u32(sm);

    float acc[2][TN][4];
#pragma unroll
    for (int i = 0; i < 2; i++)
#pragma unroll
        for (int j = 0; j < TN; j++)
#pragma unroll
            for (int q = 0; q < 4; q++) acc[i][j][q] = 0.f;

    auto prefetch = [&](int kt) {
        const int s = kt & 1;
        const long long kof = (long long)kt * 32;
#pragma unroll
        for (int h = 0; h < 2; h++) {
#pragma unroll
            for (int i = 0; i < 2; i++) {                 // A: 512 chunks / 256 thr
                int u = tid + i * 256;
                int r = u >> 2, c = (u & 3) << 3;
                cpa16(smb + (uint32_t)((( (s*2+h)*AE + swz(r, c) )) * 2),
                      gA[h] + (long long)r * K + kof + c);
            }
#pragma unroll
            for (int i = 0; i < BN / 64; i++) {           // B: BN*4 chunks
                int u = tid + i * 256;
                int r = u >> 2, c = (u & 3) << 3;
                cpa16(smb + (uint32_t)(((OFF_B + (s*2+h)*BE + swz(r, c))) * 2),
                      gB[h] + (long long)r * K + kof + c);
            }
        }
    };

    auto compute = [&](int s) {
        const uint32_t bA0 = smb + (uint32_t)((s*2    ) * AE * 2);
        const uint32_t bA1 = smb + (uint32_t)((s*2 + 1) * AE * 2);
        const uint32_t bB0 = smb + (uint32_t)((OFF_B + (s*2    ) * BE) * 2);
        const uint32_t bB1 = smb + (uint32_t)((OFF_B + (s*2 + 1) * BE) * 2);
#pragma unroll
        for (int ks = 0; ks < 2; ks++) {
            uint32_t aF[2][2][4], bF[2][TN/2][4];
            const int rA = wm * 32 + (lane & 15);
            const int cA = ks * 16 + (lane >> 4) * 8;
#pragma unroll
            for (int tm = 0; tm < 2; tm++) {
                int off = swz(rA + tm * 16, cA) * 2;
                ldsm4(aF[0][tm], bA0 + off);
                ldsm4(aF[1][tm], bA1 + off);
            }
            const int rB = wn * (BN/2) + ((lane >> 4) & 1) * 8 + (lane & 7);
            const int cB = ks * 16 + ((lane >> 3) & 1) * 8;
#pragma unroll
            for (int p = 0; p < TN/2; p++) {
                int off = swz(rB + p * 16, cB) * 2;
                ldsm4(bF[0][p], bB0 + off);
                ldsm4(bF[1][p], bB1 + off);
            }
#pragma unroll
            for (int tm = 0; tm < 2; tm++)
#pragma unroll
                for (int tn = 0; tn < TN; tn++) {
                    uint32_t* bh_ = &bF[0][tn >> 1][(tn & 1) * 2];
                    uint32_t* bl_ = &bF[1][tn >> 1][(tn & 1) * 2];
                    hmma(acc[tm][tn], aF[0][tm], bh_);
                    hmma(acc[tm][tn], aF[0][tm], bl_);
                    hmma(acc[tm][tn], aF[1][tm], bh_);
                }
        }
    };

    const int NT = K >> 5;
    prefetch(0);
    asm volatile("cp.async.commit_group;");
    for (int kt = 0; kt < NT; kt++) {
        if (kt + 1 < NT) {
            prefetch(kt + 1);
            asm volatile("cp.async.commit_group;");
            asm volatile("cp.async.wait_group 1;");
        } else {
            asm volatile("cp.async.wait_group 0;");
        }
        __syncthreads();
        compute(kt & 1);
        __syncthreads();
    }

    long long cbase = ((long long)(z >> zshift)) * sCzh
                    + ((long long)(z & ((1 << zshift) - 1))) * sCzl;
    float* Cz = C + cbase;
#pragma unroll
    for (int tm = 0; tm < 2; tm++)
#pragma unroll
        for (int tn = 0; tn < TN; tn++) {
            const int col = bn + wn * (BN/2) + tn * 8 + (lane & 3) * 2;
            const int row0 = bm + wm * 32 + tm * 16 + (lane >> 2);
            float2 bv = make_float2(0.f, 0.f);
            if (EPI != 3) bv = *(const float2*)(bias + col);
#pragma unroll
            for (int hf = 0; hf < 2; hf++) {
                const int row = row0 + hf * 8;
                float v0 = acc[tm][tn][hf*2]     + bv.x;
                float v1 = acc[tm][tn][hf*2 + 1] + bv.y;
                if (EPI == 2) { v0 = fmaxf(v0, 0.f); v1 = fmaxf(v1, 0.f); }
                if (EPI == 1) {
                    float2 rv = *(const float2*)(resid + (long long)row * ldc + col);
                    v0 += rv.x; v1 += rv.y;
                }
                float2 o; o.x = v0; o.y = v1;
                *(float2*)(Cz + (long long)row * ldc + col) = o;
            }
        }
}

// ---------------- conversions -----------------------------------------------
__device__ __forceinline__ void split1(float x, bf& h, bf& l) {
    h = __float2bfloat16(x);
    l = __float2bfloat16(x - __bfloat162float(h));
}
__device__ __forceinline__ void st4(bf* oh, bf* ol, size_t o, float a, float b, float c, float d) {
    bf h0,h1,h2,h3,l0,l1,l2,l3;
    split1(a,h0,l0); split1(b,h1,l1); split1(c,h2,l2); split1(d,h3,l3);
    __nv_bfloat162* p = (__nv_bfloat162*)(oh + o);
    __nv_bfloat162* q = (__nv_bfloat162*)(ol + o);
    __nv_bfloat162 t;
    t.x=h0; t.y=h1; p[0]=t;  t.x=h2; t.y=h3; p[1]=t;
    t.x=l0; t.y=l1; q[0]=t;  t.x=l2; t.y=l3; q[1]=t;
}
__global__ void __launch_bounds__(256) split_flat(const float* __restrict__ in, bf* oh, bf* ol) {
    size_t i4 = ((size_t)blockIdx.x * 256 + threadIdx.x) * 4;
    float4 v = *(const float4*)(in + i4);
    st4(oh, ol, i4, v.x, v.y, v.z, v.w);
}
__global__ void __launch_bounds__(256) split_qkv(const float* __restrict__ in, bf* oh, bf* ol) {
    size_t i4 = ((size_t)blockIdx.x * 256 + threadIdx.x) * 4;
    size_t bs = i4 >> 9; int hd = (int)(i4 & 511);
    int h = hd >> 6, d = hd & 63;
    size_t b = bs >> 10, s = bs & 1023;
    size_t o = (((b * HH + h) * SS) + s) * 64 + d;
    float4 v = *(const float4*)(in + i4);
    st4(oh, ol, o, v.x, v.y, v.z, v.w);
}
__global__ void __launch_bounds__(256) split_vt(const float* __restrict__ in, bf* oh, bf* ol) {
    __shared__ float t[32][33];
    int s0 = blockIdx.x * 32, d0 = blockIdx.y * 32, bh = blockIdx.z;
    int b = bh >> 3, h = bh & 7;
    int tx = threadIdx.x, ty = threadIdx.y;
#pragma unroll
    for (int j = 0; j < 4; j++)
        t[ty + j*8][tx] = in[((size_t)(b * SS + s0 + ty + j*8)) * 512 + h * 64 + d0 + tx];
    __syncthreads();
#pragma unroll
    for (int j = 0; j < 4; j++) {
        int d = d0 + ty + j*8;
        bf hh, ll; split1(t[tx][ty + j*8], hh, ll);
        size_t o = ((size_t)bh * 64 + d) * SS + s0 + tx;
        oh[o] = hh; ol[o] = ll;
    }
}
__global__ void __launch_bounds__(256) split_whead(const float* __restrict__ in, bf* oh, bf* ol) {
    __shared__ float t[32][33];
    int k0 = blockIdx.x * 32, d0 = blockIdx.y * 32, h = blockIdx.z;
    int tx = threadIdx.x, ty = threadIdx.y;
#pragma unroll
    for (int j = 0; j < 4; j++)
        t[ty + j*8][tx] = in[(size_t)h * 32768 + (size_t)(k0 + ty + j*8) * 64 + d0 + tx];
    __syncthreads();
#pragma unroll
    for (int j = 0; j < 4; j++) {
        int d = d0 + ty + j*8;
        bf hh, ll; split1(t[tx][ty + j*8], hh, ll);
        size_t o = ((size_t)(h * 64 + d)) * 512 + k0 + tx;
        oh[o] = hh; ol[o] = ll;
    }
}
__global__ void __launch_bounds__(256) softmax_kernel(
    const float* __restrict__ S, const int* __restrict__ mask, bf* ph, bf* pl)
{
    const int row = blockIdx.x;
    const int b = row >> 13;
    const float* sr = S + (size_t)row * SS;
    const int* mr = mask + b * SS;
    const int t = threadIdx.x, lane = t & 31, w = t >> 5;
    __shared__ float redm[8], reds[8];
    float4 sv = *(const float4*)(sr + t * 4);
    int4 mv = *(const int4*)(mr + t * 4);
    float v0 = mv.x ? sv.x * 0.125f : -1e10f;
    float v1 = mv.y ? sv.y * 0.125f : -1e10f;
    float v2 = mv.z ? sv.z * 0.125f : -1e10f;
    float v3 = mv.w ? sv.w * 0.125f : -1e10f;
    float mx = fmaxf(fmaxf(v0, v1), fmaxf(v2, v3));
#pragma unroll
    for (int o = 16; o; o >>= 1) mx = fmaxf(mx, __shfl_xor_sync(~0u, mx, o));
    if (lane == 0) redm[w] = mx;
    __syncthreads();
#pragma unroll
    for (int i = 0; i < 8; i++) mx = fmaxf(mx, redm[i]);
    float e0 = __expf(v0 - mx), e1 = __expf(v1 - mx);
    float e2 = __expf(v2 - mx), e3 = __expf(v3 - mx);
    float sum = e0 + e1 + e2 + e3;
#pragma unroll
    for (int o = 16; o; o >>= 1) sum += __shfl_xor_sync(~0u, sum, o);
    if (lane == 0) reds[w] = sum;
    __syncthreads();
    sum = 0.f;
#pragma unroll
    for (int i = 0; i < 8; i++) sum += reds[i];
    float inv = 1.f / sum;
    st4(ph, pl, (size_t)row * SS + (size_t)t * 4, e0*inv, e1*inv, e2*inv, e3*inv);
}

// ---------------- LayerNorm --------------------------------------------------
__global__ void __launch_bounds__(256) ln_partial_kernel(const float* __restrict__ X) {
    int b = blockIdx.x >> 8, c = blockIdx.x & 255, tid = threadIdx.x;
    const float* p = X + (size_t)b * SD + (size_t)c * 2048;
    float s = 0.f, s2 = 0.f;
#pragma unroll
    for (int i = 0; i < 8; i++) { float v = p[tid + i*256]; s += v; s2 += v*v; }
    __shared__ float sh[256], sh2[256];
    sh[tid] = s; sh2[tid] = s2; __syncthreads();
    for (int o = 128; o; o >>= 1) {
        if (tid < o) { sh[tid] += sh[tid+o]; sh2[tid] += sh2[tid+o]; }
        __syncthreads();
    }
    if (tid == 0) { g_psum[blockIdx.x] = sh[0]; g_psumsq[blockIdx.x] = sh2[0]; }
}
__global__ void __launch_bounds__(256) ln_final_kernel() {
    int b = blockIdx.x, tid = threadIdx.x;
    __shared__ float sh[256], sh2[256];
    sh[tid] = g_psum[b*256 + tid]; sh2[tid] = g_psumsq[b*256 + tid];
    __syncthreads();
    for (int o = 128; o; o >>= 1) {
        if (tid < o) { sh[tid] += sh[tid+o]; sh2[tid] += sh2[tid+o]; }
        __syncthreads();
    }
    if (tid == 0) {
        float mean = sh[0] / (float)SD;
        float var = sh2[0] / (float)SD - mean * mean;
        g_mr[2*b] = mean; g_mr[2*b+1] = rsqrtf(var + 1e-6f);
    }
}
__global__ void __launch_bounds__(256) ln_apply_kernel(
    const float* __restrict__ X, const float* __restrict__ w,
    const float* __restrict__ bb, float* __restrict__ Y)
{
    size_t base = ((size_t)blockIdx.x * 256 + threadIdx.x) * 4;
    int b = (int)(base / SD); size_t sd = base % SD;
    float mean = g_mr[2*b], rstd = g_mr[2*b+1];
    float4 xv = *(const float4*)(X + base);
    float4 wv = *(const float4*)(w + sd);
    float4 bv = *(const float4*)(bb + sd);
    float4 yv;
    yv.x = (xv.x-mean)*rstd*wv.x + bv.x; yv.y = (xv.y-mean)*rstd*wv.y + bv.y;
    yv.z = (xv.z-mean)*rstd*wv.z + bv.z; yv.w = (xv.w-mean)*rstd*wv.w + bv.w;
    *(float4*)(Y + base) = yv;
}

// ---------------- host driver ------------------------------------------------
#define SM128 65536
#define SM64  49152

struct P {
    float *q,*k,*v,*att,*res,*ff,*S;
    bf *ah,*al,*bh,*bl,*qh,*ql,*kh,*kl,*vth,*vtl,*ph,*pl;
};

static void run_ln(const float* X, const float* w, const float* b, float* Y) {
    ln_partial_kernel<<<BB*256, 256>>>(X);
    ln_final_kernel<<<BB, 256>>>();
    ln_apply_kernel<<<SD*BB/1024, 256>>>(X, w, b, Y);
}

static void mha_stage(P& p, const float* qsrc, const float* kvsrc,
    const float* wq, const float* bq, const float* wk, const float* bk,
    const float* wv, const float* bv, const float* wo, const float* bo,
    const int* mask, const float* resid, float* outres)
{
    dim3 gP(4, 64), gW(16, 2, 8), bW(32, 8);
    split_flat<<<4096, 256>>>(qsrc, p.ah, p.al);
    split_whead<<<gW, bW>>>(wq, p.bh, p.bl);
    mma_gemm<128,0><<<gP, 256, SM128>>>(p.ah, p.al, p.bh, p.bl, bq, nullptr, p.q, 512, 512, 0,0,0,0,0);
    if (kvsrc != qsrc) split_flat<<<4096, 256>>>(kvsrc, p.ah, p.al);
    split_whead<<<gW, bW>>>(wk, p.bh, p.bl);
    mma_gemm<128,0><<<gP, 256, SM128>>>(p.ah, p.al, p.bh, p.bl, bk, nullptr, p.k, 512, 512, 0,0,0,0,0);
    split_whead<<<gW, bW>>>(wv, p.bh, p.bl);
    mma_gemm<128,0><<<gP, 256, SM128>>>(p.ah, p.al, p.bh, p.bl, bv, nullptr, p.v, 512, 512, 0,0,0,0,0);

    split_qkv<<<4096, 256>>>(p.q, p.qh, p.ql);
    split_qkv<<<4096, 256>>>(p.k, p.kh, p.kl);
    split_vt<<<dim3(32, 2, 64), dim3(32, 8)>>>(p.v, p.vth, p.vtl);

    mma_gemm<128,3><<<dim3(8,8,64), 256, SM128>>>(p.qh, p.ql, p.kh, p.kl, nullptr, nullptr,
        p.S, 64, 1024, 65536, 65536, 1048576, 0, 0);
    softmax_kernel<<<NBH*SS, 256>>>(p.S, mask, p.ph, p.pl);
    mma_gemm<64,3><<<dim3(1,8,64), 256, SM64>>>(p.ph, p.pl, p.vth, p.vtl, nullptr, nullptr,
        p.att, 1024, 512, 1048576, 65536, 524288, 64, 3);

    split_flat<<<4096, 256>>>(p.att, p.ah, p.al);
    split_flat<<<256, 256>>>(wo, p.bh, p.bl);
    mma_gemm<128,1><<<gP, 256, SM128>>>(p.ah, p.al, p.bh, p.bl, bo, resid, outres, 512, 512, 0,0,0,0,0);
}

extern "C" void kernel_launch(void* const* d_in, const int* in_sizes, int n_in,
                              void* d_out, int out_size)
{
#define FP(i) ((const float*)d_in[i])
    const int* src_mask = (const int*)d_in[2];
    const int* trg_mask = (const int*)d_in[3];
    float* out = (float*)d_out;

    cudaFuncSetAttribute(mma_gemm<128,0>, cudaFuncAttributeMaxDynamicSharedMemorySize, SM128);
    cudaFuncSetAttribute(mma_gemm<128,1>, cudaFuncAttributeMaxDynamicSharedMemorySize, SM128);
    cudaFuncSetAttribute(mma_gemm<128,2>, cudaFuncAttributeMaxDynamicSharedMemorySize, SM128);
    cudaFuncSetAttribute(mma_gemm<128,3>, cudaFuncAttributeMaxDynamicSharedMemorySize, SM128);
    cudaFuncSetAttribute(mma_gemm<64,3>,  cudaFuncAttributeMaxDynamicSharedMemorySize, SM64);

    P p; float *x1, *x2;
    cudaGetSymbolAddress((void**)&p.q, g_q);   cudaGetSymbolAddress((void**)&p.k, g_k);
    cudaGetSymbolAddress((void**)&p.v, g_v);   cudaGetSymbolAddress((void**)&p.att, g_att);
    cudaGetSymbolAddress((void**)&p.res, g_res); cudaGetSymbolAddress((void**)&p.ff, g_ff);
    cudaGetSymbolAddress((void**)&p.S, g_S);
    cudaGetSymbolAddress((void**)&p.ah, g_ahh); cudaGetSymbolAddress((void**)&p.al, g_all);
    cudaGetSymbolAddress((void**)&p.bh, g_bhh); cudaGetSymbolAddress((void**)&p.bl, g_bll);
    cudaGetSymbolAddress((void**)&p.qh, g_qh);  cudaGetSymbolAddress((void**)&p.ql, g_ql);
    cudaGetSymbolAddress((void**)&p.kh, g_kh);  cudaGetSymbolAddress((void**)&p.kl, g_kl);
    cudaGetSymbolAddress((void**)&p.vth, g_vth); cudaGetSymbolAddress((void**)&p.vtl, g_vtl);
    cudaGetSymbolAddress((void**)&p.ph, g_ph);  cudaGetSymbolAddress((void**)&p.pl, g_pl);
    cudaGetSymbolAddress((void**)&x1, g_x1);    cudaGetSymbolAddress((void**)&x2, g_x2);

    // stage 1: self-attention
    mha_stage(p, FP(0), FP(0), FP(4), FP(5), FP(6), FP(7), FP(8), FP(9), FP(10), FP(11),
              trg_mask, FP(0), p.res);
    run_ln(p.res, FP(24), FP(25), x1);
    // stage 2: cross-attention
    mha_stage(p, x1, FP(1), FP(12), FP(13), FP(14), FP(15), FP(16), FP(17), FP(18), FP(19),
              src_mask, x1, p.res);
    run_ln(p.res, FP(26), FP(27), x2);
    // stage 3: FFN
    split_flat<<<4096, 256>>>(x2, p.ah, p.al);
    split_flat<<<1024, 256>>>(FP(20), p.bh, p.bl);
    mma_gemm<128,2><<<dim3(16,64), 256, SM128>>>(p.ah, p.al, p.bh, p.bl, FP(21), nullptr,
        p.ff, 512, 2048, 0,0,0,0,0);
    split_flat<<<16384, 256>>>(p.ff, p.ah, p.al);
    split_flat<<<1024, 256>>>(FP(22), p.bh, p.bl);
    mma_gemm<128,1><<<dim3(4,64), 256, SM128>>>(p.ah, p.al, p.bh, p.bl, FP(23), x2,
        p.res, 2048, 512, 0,0,0,0,0);
    run_ln(p.res, FP(28), FP(29), out);
}